// round 14
// baseline (speedup 1.0000x reference)
#include <cuda_runtime.h>
#include <cuda_fp16.h>

#define RES 512
#define RANK 32
#define CELLS (RES * RES)
#define N_POINTS (8192 * 128)

// e5m2 dup-pair layout: per plane, per cell (y,x): 64 bytes.
// Word k of 16B group j holds bytes [r@x0, r@x1, r+1@x0, r+1@x1], r = 8j+2k.
// e5m2 byte b decodes EXACTLY to the fp16 with bits (b << 8).
__device__ unsigned char g_tp[3][(size_t)CELLS * 2 * RANK];

// Encoded per-dim bbox of raw pts. Static init; graph replays are idempotent
// (atomicMin/Max of the same data over its own result is a fixed point).
__device__ unsigned int g_bbox[6] = {0xFFFFFFFFu, 0xFFFFFFFFu, 0xFFFFFFFFu, 0u, 0u, 0u};

// Affine map: grid = p * g_map[0].{x,y,z} + g_map[1].{x,y,z}
__device__ float4 g_map[2];

__device__ __forceinline__ unsigned int encodeF(float f) {
    unsigned int b = __float_as_uint(f);
    return (b & 0x80000000u) ? ~b : (b | 0x80000000u);
}
__device__ __forceinline__ float decodeF(unsigned int u) {
    return (u & 0x80000000u) ? __uint_as_float(u ^ 0x80000000u)
                             : __uint_as_float(~u);
}

// f32 -> e5m2 byte, round-to-nearest via fp16 + mantissa-rounding add.
__device__ __forceinline__ unsigned int enc_e5m2(float v) {
    const unsigned int u = (unsigned int)__half_as_ushort(__float2half_rn(v));
    return ((u + 0x80u) >> 8) & 0xFFu;
}

// ---------------------------------------------------------------------------
// Kernel 1: per-dimension min/max of raw pts + g_map compute (thread 0).
// One group (3 float4 = 4 points) per thread; warp-level REDUX reduction so
// only lane 0 of each warp touches the smem atomics (48/block, not 1536).
// ---------------------------------------------------------------------------
__global__ void __launch_bounds__(256) bbox_kernel(const float4* __restrict__ pts4,
                                                   const float* __restrict__ aabb) {
    const int g = blockIdx.x * 256 + threadIdx.x;        // group id, 0..262143
    if (g == 0) {
        float k[3], o[3];
#pragma unroll
        for (int d = 0; d < 3; d++) {
            const float a0 = aabb[d], a1 = aabb[3 + d];
            k[d] = (float)(RES - 1) / (a1 - a0);
            o[d] = -a0 * k[d];
        }
        g_map[0] = make_float4(k[0], k[1], k[2], 0.0f);
        g_map[1] = make_float4(o[0], o[1], o[2], 0.0f);
    }

    const float4 a = __ldg(&pts4[3 * g + 0]);
    const float4 b = __ldg(&pts4[3 * g + 1]);
    const float4 c = __ldg(&pts4[3 * g + 2]);
    // Warp-level reduction via REDUX on encoded values
    const unsigned int FULL = 0xffffffffu;
    const unsigned int rmnx = __reduce_min_sync(FULL, encodeF(fminf(fminf(a.x, a.w), fminf(b.z, c.y))));
    const unsigned int rmxx = __reduce_max_sync(FULL, encodeF(fmaxf(fmaxf(a.x, a.w), fmaxf(b.z, c.y))));
    const unsigned int rmny = __reduce_min_sync(FULL, encodeF(fminf(fminf(a.y, b.x), fminf(b.w, c.z))));
    const unsigned int rmxy = __reduce_max_sync(FULL, encodeF(fmaxf(fmaxf(a.y, b.x), fmaxf(b.w, c.z))));
    const unsigned int rmnz = __reduce_min_sync(FULL, encodeF(fminf(fminf(a.z, b.y), fminf(c.x, c.w))));
    const unsigned int rmxz = __reduce_max_sync(FULL, encodeF(fmaxf(fmaxf(a.z, b.y), fmaxf(c.x, c.w))));

    __shared__ unsigned int smn[3], smx[3];
    if (threadIdx.x < 3) { smn[threadIdx.x] = 0xFFFFFFFFu; smx[threadIdx.x] = 0u; }
    __syncthreads();
    if ((threadIdx.x & 31) == 0) {          // one lane per warp
        atomicMin(&smn[0], rmnx);
        atomicMin(&smn[1], rmny);
        atomicMin(&smn[2], rmnz);
        atomicMax(&smx[0], rmxx);
        atomicMax(&smx[1], rmxy);
        atomicMax(&smx[2], rmxz);
    }
    __syncthreads();
    if (threadIdx.x < 3) {
        atomicMin(&g_bbox[threadIdx.x], smn[threadIdx.x]);
        atomicMax(&g_bbox[3 + threadIdx.x], smx[threadIdx.x]);
    }
}

// ---------------------------------------------------------------------------
// Kernel 2: [RANK,H,W] f32 -> e5m2 dup-pair layout, bbox-gated.
// ---------------------------------------------------------------------------
__global__ void __launch_bounds__(256) transpose_kernel(const float* __restrict__ gxy,
                                                        const float* __restrict__ gxz,
                                                        const float* __restrict__ gyz,
                                                        const float* __restrict__ aabb) {
    const int plane = blockIdx.y;
    const int c0 = blockIdx.x * 64;
    const int row = c0 >> 9;
    const int col0 = c0 & (RES - 1);

    const int cdim = (plane == 2) ? 1 : 0;
    const int rdim = (plane == 0) ? 1 : 2;

    {   // bbox gate
        const float a0c = aabb[cdim], sc = (float)(RES - 1) / (aabb[3 + cdim] - aabb[cdim]);
        const float a0r = aabb[rdim], sr = (float)(RES - 1) / (aabb[3 + rdim] - aabb[rdim]);
        const float gminc = (decodeF(g_bbox[cdim]) - a0c) * sc;
        const float gmaxc = (decodeF(g_bbox[3 + cdim]) - a0c) * sc;
        const float gminr = (decodeF(g_bbox[rdim]) - a0r) * sr;
        const float gmaxr = (decodeF(g_bbox[3 + rdim]) - a0r) * sr;
        const int cmin = min(max(__float2int_rd(gminc), 0), RES - 1);
        const int cmax = min(min(max(__float2int_rd(gmaxc), 0), RES - 1) + 1, RES - 1);
        const int rmin = min(max(__float2int_rd(gminr), 0), RES - 1);
        const int rmax = min(min(max(__float2int_rd(gmaxr), 0), RES - 1) + 1, RES - 1);
        if (row < rmin || row > rmax || col0 > cmax || col0 + 63 < cmin) return;
    }

    __shared__ float tile[RANK][67];
    const float* __restrict__ src = (plane == 0) ? gxy : (plane == 1) ? gxz : gyz;

    const int t = threadIdx.x;

    // Load 32 ranks x 64 cols via float4
#pragma unroll
    for (int i = 0; i < 2; i++) {
        const int q = t + i * 256;
        const int r = q >> 4;
        const int c4 = (q & 15) << 2;
        const float4 v = *reinterpret_cast<const float4*>(&src[(size_t)r * CELLS + c0 + c4]);
        tile[r][c4 + 0] = v.x;
        tile[r][c4 + 1] = v.y;
        tile[r][c4 + 2] = v.z;
        tile[r][c4 + 3] = v.w;
    }
    if (t < RANK) {
        const int srccol = (col0 + 64 <= RES - 1) ? (c0 + 64) : (c0 + 63);
        tile[t][64] = src[(size_t)t * CELLS + srccol];
    }
    __syncthreads();

    {
        const int cell = t >> 2;
        const int j = t & 3;
        const int xg = col0 + cell;
        const int nb = (xg < RES - 1) ? cell + 1 : cell;
        uint4 w;
        unsigned int* wp = &w.x;
#pragma unroll
        for (int k = 0; k < 4; k++) {
            const int r0 = 8 * j + 2 * k;
            const unsigned int b0 = enc_e5m2(tile[r0][cell]);
            const unsigned int b1 = enc_e5m2(tile[r0][nb]);
            const unsigned int b2 = enc_e5m2(tile[r0 + 1][cell]);
            const unsigned int b3 = enc_e5m2(tile[r0 + 1][nb]);
            wp[k] = b0 | (b1 << 8) | (b2 << 16) | (b3 << 24);
        }
        *reinterpret_cast<uint4*>(&g_tp[plane][((size_t)(c0 + cell) << 6) + (j << 4)]) = w;
    }
}

// ---------------------------------------------------------------------------
// Kernel 3: triplane sample. 4 lanes/point; lane j = ranks 8j..8j+7.
// __launch_bounds__(256, 8): cap at 32 regs so 8 blocks (64 warps) fit per SM.
// ---------------------------------------------------------------------------
struct Corners {
    unsigned int o0, o1;   // byte offsets of (y0,x0) and (y1,x0) entries
    __half2 wx2, wy2;      // duplicated fractional weights
};

// gx/gy are final grid coords (already affinely mapped).
__device__ __forceinline__ Corners make_corners(float gx, float gy) {
    Corners c;
    c.wx2 = __float2half2_rn(gx - floorf(gx));
    c.wy2 = __float2half2_rn(gy - floorf(gy));
    const int x0 = min(max(__float2int_rd(gx), 0), RES - 1);
    const int y0 = min(max(__float2int_rd(gy), 0), RES - 1);
    const unsigned int dy = (y0 < RES - 1) ? 32768u : 0u;   // 512*64 B row stride
    c.o0 = (unsigned int)(((y0 << 9) + x0) << 6);
    c.o1 = c.o0 + dy;
    return c;
}

__device__ __forceinline__ __half2 as_h2(unsigned int u) {
    return *reinterpret_cast<__half2*>(&u);
}

// s2[k] = bilinear samples of ranks (8j+2k, 8j+2k+1), fully interpolated.
__device__ __forceinline__ void plane_sample(const uint4& E, const uint4& F,
                                             __half2 w00, __half2 w01,
                                             __half2 w10, __half2 w11,
                                             __half2 s2[4]) {
    const unsigned int* e = &E.x;
    const unsigned int* f = &F.x;
#pragma unroll
    for (int k = 0; k < 4; k++) {
        const unsigned int ex0 = __byte_perm(e[k], 0, 0x2404);  // (r@x0, r+1@x0)
        const unsigned int ex1 = e[k] & 0xFF00FF00u;            // (r@x1, r+1@x1)
        const unsigned int fx0 = __byte_perm(f[k], 0, 0x2404);
        const unsigned int fx1 = f[k] & 0xFF00FF00u;
        __half2 s = __hmul2(as_h2(ex0), w00);
        s = __hfma2(as_h2(ex1), w01, s);
        s = __hfma2(as_h2(fx0), w10, s);
        s2[k] = __hfma2(as_h2(fx1), w11, s);
    }
}

__global__ void __launch_bounds__(256, 8) sample_kernel(const float* __restrict__ pts,
                                                        float* __restrict__ out) {
    const int tid = blockIdx.x * blockDim.x + threadIdx.x;
    const int j = tid & 3;             // rank octet 0..3 (8 ranks each)
    const int point = tid >> 2;        // 4 lanes per point

    const float px = __ldg(&pts[point * 3 + 0]);
    const float py = __ldg(&pts[point * 3 + 1]);
    const float pz = __ldg(&pts[point * 3 + 2]);

    const float4 K = g_map[0];
    const float4 O = g_map[1];
    const float gxc = fmaf(px, K.x, O.x);
    const float gyc = fmaf(py, K.y, O.y);
    const float gzc = fmaf(pz, K.z, O.z);

    const Corners cxy = make_corners(gxc, gyc);
    const Corners cxz = make_corners(gxc, gzc);
    const Corners cyz = make_corners(gyc, gzc);

    const char* __restrict__ P0 = reinterpret_cast<const char*>(g_tp[0]);
    const char* __restrict__ P1 = reinterpret_cast<const char*>(g_tp[1]);
    const char* __restrict__ P2 = reinterpret_cast<const char*>(g_tp[2]);
    const unsigned int lo = (unsigned int)j << 4;

    // 6 loads; each covers a full 64 B cell entry across the 4-lane group
    const uint4 E0 = *reinterpret_cast<const uint4*>(P0 + cxy.o0 + lo);
    const uint4 F0 = *reinterpret_cast<const uint4*>(P0 + cxy.o1 + lo);
    const uint4 E1 = *reinterpret_cast<const uint4*>(P1 + cxz.o0 + lo);
    const uint4 F1 = *reinterpret_cast<const uint4*>(P1 + cxz.o1 + lo);
    const uint4 E2 = *reinterpret_cast<const uint4*>(P2 + cyz.o0 + lo);
    const uint4 F2 = *reinterpret_cast<const uint4*>(P2 + cyz.o1 + lo);

    // Weights built in fp16: 2 HSUB2 + 4 HMUL2 per plane
    const __half2 ONE = __float2half2_rn(1.0f);
    const __half2 ox0 = __hsub2(ONE, cxy.wx2), oy0 = __hsub2(ONE, cxy.wy2);
    const __half2 ox1 = __hsub2(ONE, cxz.wx2), oy1 = __hsub2(ONE, cxz.wy2);
    const __half2 ox2 = __hsub2(ONE, cyz.wx2), oy2 = __hsub2(ONE, cyz.wy2);

    __half2 sA[4], sB[4], sC[4];
    plane_sample(E0, F0, __hmul2(ox0, oy0), __hmul2(cxy.wx2, oy0),
                 __hmul2(ox0, cxy.wy2), __hmul2(cxy.wx2, cxy.wy2), sA);
    plane_sample(E1, F1, __hmul2(ox1, oy1), __hmul2(cxz.wx2, oy1),
                 __hmul2(ox1, cxz.wy2), __hmul2(cxz.wx2, cxz.wy2), sB);
    plane_sample(E2, F2, __hmul2(ox2, oy2), __hmul2(cyz.wx2, oy2),
                 __hmul2(ox2, cyz.wy2), __hmul2(cyz.wx2, cyz.wy2), sC);

    // Triple product + accumulate, 2 ranks per op
    __half2 acc = __hmul2(__hmul2(sA[0], sB[0]), sC[0]);
#pragma unroll
    for (int k = 1; k < 4; k++) {
        acc = __hfma2(__hmul2(sA[k], sB[k]), sC[k], acc);
    }
    float sum = __low2float(acc) + __high2float(acc);

    // Reduce across the 4-lane group
    sum += __shfl_xor_sync(0xffffffffu, sum, 1, 4);
    sum += __shfl_xor_sync(0xffffffffu, sum, 2, 4);

    if (j == 0) {
        out[point] = __expf(sum * (1.0f / (float)RANK));
    }
}

extern "C" void kernel_launch(void* const* d_in, const int* in_sizes, int n_in,
                              void* d_out, int out_size) {
    const float* pts  = (const float*)d_in[0];
    const float* gxy  = (const float*)d_in[1];
    const float* gxz  = (const float*)d_in[2];
    const float* gyz  = (const float*)d_in[3];
    const float* aabb = (const float*)d_in[4];
    float* out = (float*)d_out;

    // 262144 groups, 1 per thread
    bbox_kernel<<<1024, 256>>>((const float4*)pts, aabb);
    transpose_kernel<<<dim3(CELLS / 64, 3), 256>>>(gxy, gxz, gyz, aabb);

    // 4 lanes/point -> 64 points per 256-thread block
    sample_kernel<<<N_POINTS / 64, 256>>>(pts, out);
}

// round 15
// speedup vs baseline: 1.0012x; 1.0012x over previous
#include <cuda_runtime.h>
#include <cuda_fp16.h>

#define RES 512
#define RANK 32
#define CELLS (RES * RES)
#define N_POINTS (8192 * 128)

// e5m2 dup-pair layout: per plane, per cell (y,x): 64 bytes.
// Word k of 16B group j holds bytes [r@x0, r@x1, r+1@x0, r+1@x1], r = 8j+2k.
// e5m2 byte b decodes EXACTLY to the fp16 with bits (b << 8).
// Plane stride = CELLS*64 = 0x1000000 bytes.
__device__ unsigned char g_tp[3][(size_t)CELLS * 2 * RANK];

// Encoded per-dim bbox of raw pts. Static init; graph replays are idempotent.
__device__ unsigned int g_bbox[6] = {0xFFFFFFFFu, 0xFFFFFFFFu, 0xFFFFFFFFu, 0u, 0u, 0u};

// Affine map: grid = p * g_map[0].{x,y,z} + g_map[1].{x,y,z}
__device__ float4 g_map[2];

__device__ __forceinline__ unsigned int encodeF(float f) {
    unsigned int b = __float_as_uint(f);
    return (b & 0x80000000u) ? ~b : (b | 0x80000000u);
}
__device__ __forceinline__ float decodeF(unsigned int u) {
    return (u & 0x80000000u) ? __uint_as_float(u ^ 0x80000000u)
                             : __uint_as_float(~u);
}

// HW pack-convert: 2 x f32 -> packed e5m2 pair. Result: bits[15:8]=e5m2(hi), [7:0]=e5m2(lo).
__device__ __forceinline__ unsigned short enc2_e5m2(float hi, float lo) {
    unsigned short r;
    asm("cvt.rn.satfinite.e5m2x2.f32 %0, %1, %2;" : "=h"(r) : "f"(hi), "f"(lo));
    return r;
}

// ---------------------------------------------------------------------------
// Kernel 1: per-dimension min/max of raw pts + g_map compute (thread 0).
// One group (3 float4 = 4 points) per thread; warp REDUX, lane 0 does atomics.
// ---------------------------------------------------------------------------
__global__ void __launch_bounds__(256) bbox_kernel(const float4* __restrict__ pts4,
                                                   const float* __restrict__ aabb) {
    const int g = blockIdx.x * 256 + threadIdx.x;        // group id, 0..262143
    if (g == 0) {
        float k[3], o[3];
#pragma unroll
        for (int d = 0; d < 3; d++) {
            const float a0 = aabb[d], a1 = aabb[3 + d];
            k[d] = (float)(RES - 1) / (a1 - a0);
            o[d] = -a0 * k[d];
        }
        g_map[0] = make_float4(k[0], k[1], k[2], 0.0f);
        g_map[1] = make_float4(o[0], o[1], o[2], 0.0f);
    }

    const float4 a = __ldg(&pts4[3 * g + 0]);
    const float4 b = __ldg(&pts4[3 * g + 1]);
    const float4 c = __ldg(&pts4[3 * g + 2]);
    const unsigned int FULL = 0xffffffffu;
    const unsigned int rmnx = __reduce_min_sync(FULL, encodeF(fminf(fminf(a.x, a.w), fminf(b.z, c.y))));
    const unsigned int rmxx = __reduce_max_sync(FULL, encodeF(fmaxf(fmaxf(a.x, a.w), fmaxf(b.z, c.y))));
    const unsigned int rmny = __reduce_min_sync(FULL, encodeF(fminf(fminf(a.y, b.x), fminf(b.w, c.z))));
    const unsigned int rmxy = __reduce_max_sync(FULL, encodeF(fmaxf(fmaxf(a.y, b.x), fmaxf(b.w, c.z))));
    const unsigned int rmnz = __reduce_min_sync(FULL, encodeF(fminf(fminf(a.z, b.y), fminf(c.x, c.w))));
    const unsigned int rmxz = __reduce_max_sync(FULL, encodeF(fmaxf(fmaxf(a.z, b.y), fmaxf(c.x, c.w))));

    __shared__ unsigned int smn[3], smx[3];
    if (threadIdx.x < 3) { smn[threadIdx.x] = 0xFFFFFFFFu; smx[threadIdx.x] = 0u; }
    __syncthreads();
    if ((threadIdx.x & 31) == 0) {
        atomicMin(&smn[0], rmnx);
        atomicMin(&smn[1], rmny);
        atomicMin(&smn[2], rmnz);
        atomicMax(&smx[0], rmxx);
        atomicMax(&smx[1], rmxy);
        atomicMax(&smx[2], rmxz);
    }
    __syncthreads();
    if (threadIdx.x < 3) {
        atomicMin(&g_bbox[threadIdx.x], smn[threadIdx.x]);
        atomicMax(&g_bbox[3 + threadIdx.x], smx[threadIdx.x]);
    }
}

// ---------------------------------------------------------------------------
// Kernel 2: [RANK,H,W] f32 -> e5m2 dup-pair layout, bbox-gated.
// HW e5m2x2 pack-convert: 3 insts per output word (was ~17).
// ---------------------------------------------------------------------------
__global__ void __launch_bounds__(256) transpose_kernel(const float* __restrict__ gxy,
                                                        const float* __restrict__ gxz,
                                                        const float* __restrict__ gyz,
                                                        const float* __restrict__ aabb) {
    const int plane = blockIdx.y;
    const int c0 = blockIdx.x * 64;
    const int row = c0 >> 9;
    const int col0 = c0 & (RES - 1);

    const int cdim = (plane == 2) ? 1 : 0;
    const int rdim = (plane == 0) ? 1 : 2;

    {   // bbox gate
        const float a0c = aabb[cdim], sc = (float)(RES - 1) / (aabb[3 + cdim] - aabb[cdim]);
        const float a0r = aabb[rdim], sr = (float)(RES - 1) / (aabb[3 + rdim] - aabb[rdim]);
        const float gminc = (decodeF(g_bbox[cdim]) - a0c) * sc;
        const float gmaxc = (decodeF(g_bbox[3 + cdim]) - a0c) * sc;
        const float gminr = (decodeF(g_bbox[rdim]) - a0r) * sr;
        const float gmaxr = (decodeF(g_bbox[3 + rdim]) - a0r) * sr;
        const int cmin = min(max(__float2int_rd(gminc), 0), RES - 1);
        const int cmax = min(min(max(__float2int_rd(gmaxc), 0), RES - 1) + 1, RES - 1);
        const int rmin = min(max(__float2int_rd(gminr), 0), RES - 1);
        const int rmax = min(min(max(__float2int_rd(gmaxr), 0), RES - 1) + 1, RES - 1);
        if (row < rmin || row > rmax || col0 > cmax || col0 + 63 < cmin) return;
    }

    __shared__ float tile[RANK][67];
    const float* __restrict__ src = (plane == 0) ? gxy : (plane == 1) ? gxz : gyz;

    const int t = threadIdx.x;

    // Load 32 ranks x 64 cols via float4
#pragma unroll
    for (int i = 0; i < 2; i++) {
        const int q = t + i * 256;
        const int r = q >> 4;
        const int c4 = (q & 15) << 2;
        const float4 v = *reinterpret_cast<const float4*>(&src[(size_t)r * CELLS + c0 + c4]);
        tile[r][c4 + 0] = v.x;
        tile[r][c4 + 1] = v.y;
        tile[r][c4 + 2] = v.z;
        tile[r][c4 + 3] = v.w;
    }
    if (t < RANK) {
        const int srccol = (col0 + 64 <= RES - 1) ? (c0 + 64) : (c0 + 63);
        tile[t][64] = src[(size_t)t * CELLS + srccol];
    }
    __syncthreads();

    {
        const int cell = t >> 2;
        const int j = t & 3;
        const int xg = col0 + cell;
        const int nb = (xg < RES - 1) ? cell + 1 : cell;
        uint4 w;
        unsigned int* wp = &w.x;
#pragma unroll
        for (int k = 0; k < 4; k++) {
            const int r0 = 8 * j + 2 * k;
            const unsigned short lo16 = enc2_e5m2(tile[r0][nb], tile[r0][cell]);     // [x1|x0]
            const unsigned short hi16 = enc2_e5m2(tile[r0 + 1][nb], tile[r0 + 1][cell]);
            wp[k] = ((unsigned int)hi16 << 16) | (unsigned int)lo16;
        }
        *reinterpret_cast<uint4*>(&g_tp[plane][((size_t)(c0 + cell) << 6) + (j << 4)]) = w;
    }
}

// ---------------------------------------------------------------------------
// Kernel 3: triplane sample. 4 lanes/point; lane j = ranks 8j..8j+7.
// ---------------------------------------------------------------------------
struct Corners {
    unsigned int o0, o1;   // byte offsets of (y0,x0) and (y1,x0) entries
    __half2 wx2, wy2;      // duplicated fractional weights
};

__device__ __forceinline__ Corners make_corners(float gx, float gy) {
    Corners c;
    c.wx2 = __float2half2_rn(gx - floorf(gx));
    c.wy2 = __float2half2_rn(gy - floorf(gy));
    const int x0 = min(max(__float2int_rd(gx), 0), RES - 1);
    const int y0 = min(max(__float2int_rd(gy), 0), RES - 1);
    const unsigned int dy = (y0 < RES - 1) ? 32768u : 0u;   // 512*64 B row stride
    c.o0 = (unsigned int)(((y0 << 9) + x0) << 6);
    c.o1 = c.o0 + dy;
    return c;
}

__device__ __forceinline__ __half2 as_h2(unsigned int u) {
    return *reinterpret_cast<__half2*>(&u);
}

// s2[k] = bilinear samples of ranks (8j+2k, 8j+2k+1), fully interpolated.
__device__ __forceinline__ void plane_sample(const uint4& E, const uint4& F,
                                             __half2 w00, __half2 w01,
                                             __half2 w10, __half2 w11,
                                             __half2 s2[4]) {
    const unsigned int* e = &E.x;
    const unsigned int* f = &F.x;
#pragma unroll
    for (int k = 0; k < 4; k++) {
        const unsigned int ex0 = __byte_perm(e[k], 0, 0x2404);  // (r@x0, r+1@x0)
        const unsigned int ex1 = e[k] & 0xFF00FF00u;            // (r@x1, r+1@x1)
        const unsigned int fx0 = __byte_perm(f[k], 0, 0x2404);
        const unsigned int fx1 = f[k] & 0xFF00FF00u;
        __half2 s = __hmul2(as_h2(ex0), w00);
        s = __hfma2(as_h2(ex1), w01, s);
        s = __hfma2(as_h2(fx0), w10, s);
        s2[k] = __hfma2(as_h2(fx1), w11, s);
    }
}

__global__ void __launch_bounds__(256, 8) sample_kernel(const float* __restrict__ pts,
                                                        float* __restrict__ out) {
    const int tid = blockIdx.x * blockDim.x + threadIdx.x;
    const int j = tid & 3;             // rank octet 0..3 (8 ranks each)
    const int point = tid >> 2;        // 4 lanes per point

    const float px = __ldg(&pts[point * 3 + 0]);
    const float py = __ldg(&pts[point * 3 + 1]);
    const float pz = __ldg(&pts[point * 3 + 2]);

    const float4 K = g_map[0];
    const float4 O = g_map[1];
    const float gxc = fmaf(px, K.x, O.x);
    const float gyc = fmaf(py, K.y, O.y);
    const float gzc = fmaf(pz, K.z, O.z);

    const Corners cxy = make_corners(gxc, gyc);
    const Corners cxz = make_corners(gxc, gzc);
    const Corners cyz = make_corners(gyc, gzc);

    // Single base pointer; plane stride folded into 32-bit offsets.
    const char* __restrict__ B = reinterpret_cast<const char*>(g_tp);
    const unsigned int lo = (unsigned int)j << 4;
    const unsigned int oa0 = cxy.o0 + lo,              oa1 = cxy.o1 + lo;
    const unsigned int ob0 = cxz.o0 + lo + 0x1000000u, ob1 = cxz.o1 + lo + 0x1000000u;
    const unsigned int oc0 = cyz.o0 + lo + 0x2000000u, oc1 = cyz.o1 + lo + 0x2000000u;

    const uint4 E0 = *reinterpret_cast<const uint4*>(B + oa0);
    const uint4 F0 = *reinterpret_cast<const uint4*>(B + oa1);
    const uint4 E1 = *reinterpret_cast<const uint4*>(B + ob0);
    const uint4 F1 = *reinterpret_cast<const uint4*>(B + ob1);
    const uint4 E2 = *reinterpret_cast<const uint4*>(B + oc0);
    const uint4 F2 = *reinterpret_cast<const uint4*>(B + oc1);

    // Weights built in fp16: 2 HSUB2 + 4 HMUL2 per plane
    const __half2 ONE = __float2half2_rn(1.0f);
    const __half2 ox0 = __hsub2(ONE, cxy.wx2), oy0 = __hsub2(ONE, cxy.wy2);
    const __half2 ox1 = __hsub2(ONE, cxz.wx2), oy1 = __hsub2(ONE, cxz.wy2);
    const __half2 ox2 = __hsub2(ONE, cyz.wx2), oy2 = __hsub2(ONE, cyz.wy2);

    __half2 sA[4], sB[4], sC[4];
    plane_sample(E0, F0, __hmul2(ox0, oy0), __hmul2(cxy.wx2, oy0),
                 __hmul2(ox0, cxy.wy2), __hmul2(cxy.wx2, cxy.wy2), sA);
    plane_sample(E1, F1, __hmul2(ox1, oy1), __hmul2(cxz.wx2, oy1),
                 __hmul2(ox1, cxz.wy2), __hmul2(cxz.wx2, cxz.wy2), sB);
    plane_sample(E2, F2, __hmul2(ox2, oy2), __hmul2(cyz.wx2, oy2),
                 __hmul2(ox2, cyz.wy2), __hmul2(cyz.wx2, cyz.wy2), sC);

    // Triple product + accumulate, 2 ranks per op
    __half2 acc = __hmul2(__hmul2(sA[0], sB[0]), sC[0]);
#pragma unroll
    for (int k = 1; k < 4; k++) {
        acc = __hfma2(__hmul2(sA[k], sB[k]), sC[k], acc);
    }
    float sum = __low2float(acc) + __high2float(acc);

    // Reduce across the 4-lane group
    sum += __shfl_xor_sync(0xffffffffu, sum, 1, 4);
    sum += __shfl_xor_sync(0xffffffffu, sum, 2, 4);

    if (j == 0) {
        // exp(sum/32) = exp2(sum * log2(e)/32), single FMUL + EX2
        out[point] = exp2f(sum * 0.045084220f);
    }
}

extern "C" void kernel_launch(void* const* d_in, const int* in_sizes, int n_in,
                              void* d_out, int out_size) {
    const float* pts  = (const float*)d_in[0];
    const float* gxy  = (const float*)d_in[1];
    const float* gxz  = (const float*)d_in[2];
    const float* gyz  = (const float*)d_in[3];
    const float* aabb = (const float*)d_in[4];
    float* out = (float*)d_out;

    bbox_kernel<<<1024, 256>>>((const float4*)pts, aabb);
    transpose_kernel<<<dim3(CELLS / 64, 3), 256>>>(gxy, gxz, gyz, aabb);
    sample_kernel<<<N_POINTS / 64, 256>>>(pts, out);
}